// round 11
// baseline (speedup 1.0000x reference)
#include <cuda_runtime.h>
#include <cuda_bf16.h>
#include <cstdint>
#include <cstddef>

// ---------------------------------------------------------------------------
// QuantizedLinear via int8 mma.sync (base sm_100 ISA; tcgen05 rejected by the
// harness's compute_100 PTX target).
//
// out[m,n] = acc[m,n]*alpha[n] + beta[n]
//   acc   = sum_k q(x[m,k]) * w[n,k]            (exact s32)
//   q(x)  = clamp(rint(x/sa + zp), -128, 127)
//   alpha = ws[n]*sa ; beta = bias[n] - zp*(sum_k w[n,k])*alpha
//
// R11 (= R10 resubmit after infra failure; deadlock-freedom re-audited:
//      m-flag contributors are contiguous block indices so wave 1 always
//      contains complete groups -> guaranteed progress):
//      fused prep: every GEMM CTA quantizes its own 16-row x-slice (8 CTAs
//      cover one m-tile); CTAs 0..7 convert W + alpha/beta; release/acquire
//      flag protocol (volatile-load spin, threadfence acquire); flag-reset
//      kernel keeps graph replays deterministic. GEMM core = R7.
// ---------------------------------------------------------------------------

#define K_DIM    1024
#define N_DIM    1024
#define M_MAX    16384
#define M_TILE   128
#define N_TILE   128
#define K_TILE   128
#define K_CHUNKS (K_DIM / K_TILE)        // 8
#define STAGES   3
#define THREADS  256

#define M_TILES  (M_MAX / M_TILE)         // 128
#define N_TILES  (N_DIM / N_TILE)         // 8
#define GRID     (M_TILES * N_TILES)      // 1024

#define SMEM_STRIDE 144                   // 128B row + 16B pad (conflict-free)
#define A_BYTES   (M_TILE * SMEM_STRIDE)  // 18432
#define B_BYTES   (N_TILE * SMEM_STRIDE)  // 18432
#define STAGE_BYTES (A_BYTES + B_BYTES)   // 36864
#define SMEM_TOTAL (STAGES * STAGE_BYTES) // 110592 per CTA (2 CTAs/SM)

__device__ __align__(16) int8_t g_A[(size_t)M_MAX * K_DIM];  // 16 MB
__device__ __align__(16) int8_t g_W[(size_t)N_DIM * K_DIM];  //  1 MB
__device__ float g_alpha[N_DIM];
__device__ float g_beta[N_DIM];
__device__ int   g_mflag[M_TILES];        // 8 contributors each
__device__ int   g_nflag[N_TILES];        // 1 contributor each

// ------------------------------- PTX helpers -------------------------------

__device__ __forceinline__ uint32_t smem_u32(const void* p) {
    return (uint32_t)__cvta_generic_to_shared(p);
}
__device__ __forceinline__ void cp_async16(uint32_t dst, const void* src) {
    asm volatile("cp.async.cg.shared.global [%0], [%1], 16;"
                 :: "r"(dst), "l"(src) : "memory");
}
__device__ __forceinline__ void cp_commit() {
    asm volatile("cp.async.commit_group;" ::: "memory");
}
__device__ __forceinline__ void cp_wait1() {
    asm volatile("cp.async.wait_group 1;" ::: "memory");
}
__device__ __forceinline__ void mma_s8(int* c, const uint32_t* a,
                                       uint32_t b0, uint32_t b1) {
    asm volatile(
        "mma.sync.aligned.m16n8k32.row.col.s32.s8.s8.s32 "
        "{%0,%1,%2,%3}, {%4,%5,%6,%7}, {%8,%9}, {%0,%1,%2,%3};"
        : "+r"(c[0]), "+r"(c[1]), "+r"(c[2]), "+r"(c[3])
        : "r"(a[0]), "r"(a[1]), "r"(a[2]), "r"(a[3]), "r"(b0), "r"(b1));
}
__device__ __forceinline__ void ldsm_x4(uint32_t* r, uint32_t addr) {
    asm volatile("ldmatrix.sync.aligned.m8n8.x4.shared.b16 {%0,%1,%2,%3}, [%4];"
                 : "=r"(r[0]), "=r"(r[1]), "=r"(r[2]), "=r"(r[3]) : "r"(addr));
}
__device__ __forceinline__ int ld_volatile(const int* p) {
    int v;
    asm volatile("ld.volatile.global.s32 %0, [%1];" : "=r"(v) : "l"(p));
    return v;
}
__device__ __forceinline__ int q8(float v, float inv, float zp) {
    // mul-then-add (no FMA contraction) matches jnp; rintf = round-half-even
    return (int)fminf(fmaxf(rintf(__fadd_rn(__fmul_rn(v, inv), zp)), -128.f), 127.f);
}

// --------------------------- flag reset (per call) --------------------------

__global__ void reset_kernel() {
    int t = threadIdx.x;
    if (t < M_TILES) g_mflag[t] = 0;
    if (t < N_TILES) g_nflag[t] = 0;
}

// --------------------------- fused prep + GEMM ------------------------------
// CTA b: m-tile mt=b>>3, n-tile nt=b&7.
//   preamble 1: quantize x rows [mt*128 + nt*16, +16) -> g_A
//   preamble 2 (b<8): convert W n-tile b (128 rows) -> g_W, alpha/beta
//   release (atomicAdd) ; acquire (volatile spin + threadfence)
//   then R7 mainloop: K_TILE=128, 3-stage cp.async, stride-144, ldmatrix.x4,
//   ping-pong A prefetch; fused alpha/beta epilogue.

__global__ __launch_bounds__(THREADS, 2)
void gemm_kernel(float* __restrict__ out,
                 const float* __restrict__ x,
                 const int* __restrict__ wint,
                 const float* __restrict__ wsc,
                 const float* __restrict__ asc,
                 const float* __restrict__ azp,
                 const float* __restrict__ bias) {
    extern __shared__ char smem[];
    uint32_t sbase = smem_u32(smem);

    const int tid  = threadIdx.x;
    const int wid  = tid >> 5;
    const int lane = tid & 31;
    const int g = lane >> 2;
    const int q = lane & 3;

    const int bid = blockIdx.x;
    const int mt  = bid >> 3;
    const int nt  = bid & 7;
    const int m0  = mt * M_TILE;
    const int n0  = nt * N_TILE;

    // ---- preamble 1: quantize my 16-row slice of x ----
    {
        float inv = 1.0f / asc[0];
        float zp  = azp[0];
        size_t base8 = ((size_t)(m0 + nt * 16) * K_DIM) >> 3;  // 8-float units
        const float4* xp = reinterpret_cast<const float4*>(x);
#pragma unroll
        for (int it = 0; it < 8; it++) {
            size_t i = base8 + tid + it * 256;
            float4 v0, v1;
            asm volatile("ld.global.cs.v4.f32 {%0,%1,%2,%3}, [%4];"
                         : "=f"(v0.x), "=f"(v0.y), "=f"(v0.z), "=f"(v0.w)
                         : "l"(xp + 2 * i));
            asm volatile("ld.global.cs.v4.f32 {%0,%1,%2,%3}, [%4];"
                         : "=f"(v1.x), "=f"(v1.y), "=f"(v1.z), "=f"(v1.w)
                         : "l"(xp + 2 * i + 1));
            uint2 pck;
            pck.x = (uint32_t)(q8(v0.x, inv, zp) & 0xFF) |
                    ((uint32_t)(q8(v0.y, inv, zp) & 0xFF) << 8) |
                    ((uint32_t)(q8(v0.z, inv, zp) & 0xFF) << 16) |
                    ((uint32_t)(q8(v0.w, inv, zp) & 0xFF) << 24);
            pck.y = (uint32_t)(q8(v1.x, inv, zp) & 0xFF) |
                    ((uint32_t)(q8(v1.y, inv, zp) & 0xFF) << 8) |
                    ((uint32_t)(q8(v1.z, inv, zp) & 0xFF) << 16) |
                    ((uint32_t)(q8(v1.w, inv, zp) & 0xFF) << 24);
            reinterpret_cast<uint2*>(g_A)[i] = pck;
        }
    }

    // ---- preamble 2 (CTAs 0..7): convert W n-tile bid ----
    if (bid < 8) {
        float sa = asc[0];
        float zp = azp[0];
        int row0 = bid * 128 + wid * 16;          // warp -> 16 rows
        for (int j = 0; j < 16; j++) {
            int row = row0 + j;
            const int4* rp = reinterpret_cast<const int4*>(
                wint + (size_t)row * K_DIM);
            uint32_t* wp = reinterpret_cast<uint32_t*>(g_W + (size_t)row * K_DIM);
            float sum = 0.f;
#pragma unroll
            for (int i = 0; i < 8; i++) {
                int4 v = rp[lane + i * 32];
                sum += (float)(v.x + v.y + v.z + v.w);
                wp[lane + i * 32] =
                    (uint32_t)(v.x & 0xFF) | ((uint32_t)(v.y & 0xFF) << 8) |
                    ((uint32_t)(v.z & 0xFF) << 16) | ((uint32_t)(v.w & 0xFF) << 24);
            }
#pragma unroll
            for (int s = 16; s > 0; s >>= 1)
                sum += __shfl_xor_sync(0xFFFFFFFFu, sum, s);
            if (lane == 0) {
                float alpha = wsc[row] * sa;
                g_alpha[row] = alpha;
                g_beta[row]  = bias[row] - zp * sum * alpha;
            }
        }
    }

    // ---- release + acquire ----
    __threadfence();
    __syncthreads();
    if (tid == 0) {
        atomicAdd(&g_mflag[mt], 1);
        if (bid < 8) atomicAdd(&g_nflag[bid], 1);
        while (ld_volatile(&g_mflag[mt]) < 8) __nanosleep(128);
        while (ld_volatile(&g_nflag[nt]) < 1) __nanosleep(128);
        __threadfence();
    }
    __syncthreads();

    // ------------------------- R7 GEMM mainloop ----------------------------
    const int wm = wid & 1;                   // 0..1 (64 rows)
    const int wn = wid >> 1;                  // 0..3 (32 cols)

    const int lrow = tid >> 3;                // 0..31
    const int lcol = (tid & 7) * 16;          // 0..112
    const int8_t* src_a = g_A + (size_t)(m0 + lrow) * K_DIM + lcol;
    const int8_t* src_b = g_W + (size_t)(n0 + lrow) * K_DIM + lcol;
    const uint32_t dst_a = (uint32_t)(lrow * SMEM_STRIDE + lcol);
    const uint32_t dst_b = dst_a + A_BYTES;

    auto load_chunk = [&](int kc, uint32_t stage) {
#pragma unroll
        for (int j = 0; j < 4; j++)
            cp_async16(stage + dst_a + j * 32 * SMEM_STRIDE,
                       src_a + kc * K_TILE + (size_t)j * 32 * K_DIM);
#pragma unroll
        for (int j = 0; j < 4; j++)
            cp_async16(stage + dst_b + j * 32 * SMEM_STRIDE,
                       src_b + kc * K_TILE + (size_t)j * 32 * K_DIM);
    };

    load_chunk(0, sbase);
    cp_commit();
    load_chunk(1, sbase + STAGE_BYTES);
    cp_commit();

    int acc[4][4][4];                          // [mf][nf][c]
#pragma unroll
    for (int mf = 0; mf < 4; mf++)
#pragma unroll
        for (int nf = 0; nf < 4; nf++)
#pragma unroll
            for (int i = 0; i < 4; i++) acc[mf][nf][i] = 0;

    const uint32_t inv_a = (uint32_t)((wm * 64 + (lane & 15)) * SMEM_STRIDE
                                      + ((lane >> 4) << 4));
    const uint32_t inv_b = (uint32_t)(A_BYTES
                                      + (wn * 32 + ((lane >> 4) & 1) * 8 + (lane & 7)) * SMEM_STRIDE
                                      + ((lane >> 3) & 1) * 16);

    uint32_t afrag[2][4][4];
    int stage_idx = 0;

    for (int kc = 0; kc < K_CHUNKS; kc++) {
        cp_wait1();
        __syncthreads();

        int kl = kc + 2;
        if (kl < K_CHUNKS) {
            int sl = stage_idx + 2;
            if (sl >= STAGES) sl -= STAGES;
            load_chunk(kl, sbase + (uint32_t)sl * STAGE_BYTES);
        }
        cp_commit();                           // empty group at tail keeps count

        uint32_t stage = sbase + (uint32_t)stage_idx * STAGE_BYTES;
        if (++stage_idx == STAGES) stage_idx = 0;

#pragma unroll
        for (int mf = 0; mf < 4; mf++)
            ldsm_x4(afrag[0][mf], stage + inv_a + (uint32_t)(mf * 16 * SMEM_STRIDE));

#pragma unroll
        for (int ks = 0; ks < 4; ks++) {       // four k=32 steps per chunk
            uint32_t ko = (uint32_t)(ks * 32);
            uint32_t b[2][4];
#pragma unroll
            for (int np = 0; np < 2; np++)
                ldsm_x4(b[np], stage + inv_b + (uint32_t)(np * 16 * SMEM_STRIDE) + ko);
            if (ks < 3) {
#pragma unroll
                for (int mf = 0; mf < 4; mf++)
                    ldsm_x4(afrag[(ks + 1) & 1][mf],
                            stage + inv_a + (uint32_t)(mf * 16 * SMEM_STRIDE) + ko + 32);
            }
            const uint32_t (*a)[4] = afrag[ks & 1];
#pragma unroll
            for (int nf = 0; nf < 4; nf++) {
                uint32_t b0 = b[nf >> 1][(nf & 1) * 2];
                uint32_t b1 = b[nf >> 1][(nf & 1) * 2 + 1];
#pragma unroll
                for (int mf = 0; mf < 4; mf++)
                    mma_s8(acc[mf][nf], a[mf], b0, b1);
            }
        }
    }

    // ---- epilogue: y = acc*alpha[n] + beta[n], float2 stores ----
#pragma unroll
    for (int nf = 0; nf < 4; nf++) {
        int col = n0 + wn * 32 + nf * 8 + 2 * q;
        float2 al = *reinterpret_cast<const float2*>(&g_alpha[col]);
        float2 be = *reinterpret_cast<const float2*>(&g_beta[col]);
#pragma unroll
        for (int mf = 0; mf < 4; mf++) {
            int row = m0 + wm * 64 + mf * 16 + g;
            float2 v0, v1;
            v0.x = (float)acc[mf][nf][0] * al.x + be.x;
            v0.y = (float)acc[mf][nf][1] * al.y + be.y;
            v1.x = (float)acc[mf][nf][2] * al.x + be.x;
            v1.y = (float)acc[mf][nf][3] * al.y + be.y;
            *reinterpret_cast<float2*>(out + (size_t)row * N_DIM + col) = v0;
            *reinterpret_cast<float2*>(out + (size_t)(row + 8) * N_DIM + col) = v1;
        }
    }
}

// ------------------------------- launcher ----------------------------------
// Single stream, two launches, no stream/event creation (capture-safe,
// allocation-free). reset_kernel re-zeroes the flags so every graph replay
// performs identical work.

extern "C" void kernel_launch(void* const* d_in, const int* in_sizes, int n_in,
                              void* d_out, int out_size) {
    const float* x    = (const float*)d_in[0];   // [B,S,IN] fp32
    const int*   wint = (const int*)  d_in[1];   // [OUT,IN] int32
    const float* wsc  = (const float*)d_in[2];   // [OUT]
    const float* asc  = (const float*)d_in[3];   // [1]
    const float* azp  = (const float*)d_in[4];   // [1]
    const float* bias = (const float*)d_in[5];   // [OUT]
    float* out = (float*)d_out;

    cudaFuncSetAttribute(gemm_kernel,
                         cudaFuncAttributeMaxDynamicSharedMemorySize, SMEM_TOTAL);

    reset_kernel<<<1, THREADS>>>();
    gemm_kernel<<<GRID, THREADS, SMEM_TOTAL>>>(out, x, wint, wsc, asc, azp, bias);
}